// round 2
// baseline (speedup 1.0000x reference)
#include <cuda_runtime.h>

#define Hh 64
#define Ww 64
#define Bb 32
#define CIN 16
#define COUT 32
#define Pp 144           // CIN * 3 * 3

typedef unsigned long long u64;

__device__ __forceinline__ void fma2(u64& d, u64 a, u64 b) {
    asm("fma.rn.f32x2 %0, %1, %2, %0;" : "+l"(d) : "l"(a), "l"(b));
}
__device__ __forceinline__ u64 pack2(float v) {
    u64 r;
    asm("mov.b64 %0, {%1, %1};" : "=l"(r) : "f"(v));
    return r;
}
__device__ __forceinline__ void unpack2(u64 d, float& lo, float& hi) {
    asm("mov.b64 {%0, %1}, %2;" : "=f"(lo), "=f"(hi) : "l"(d));
}

__global__ __launch_bounds__(64) void xonv_kernel(
    const float* __restrict__ x,        // (B, CIN, H, W)
    const float* __restrict__ weights,  // (H, W, COUT, CIN, 3, 3)
    const float* __restrict__ bias,     // (H, W, COUT)
    float* __restrict__ out)            // (B, COUT, H, W)
{
    // Transposed layouts, stride 32 (conflict-free for both staging and compute)
    __shared__ float wsT[Pp][COUT];     // [144][32]  w for this location, p-major rows
    __shared__ float xsT[Pp][Bb];       // [144][32]  im2col patches, p-major rows
    __shared__ float bs[COUT];

    const int loc = blockIdx.x;          // 0..4095
    const int h   = loc >> 6;
    const int w   = loc & 63;
    const int tid = threadIdx.x;         // 0..63
    const int lane32 = tid & 31;

    // ---------------- stage weights (transpose to wsT[p][o]) ----------------
    // chunk g = o*36 + pc covers 1152 float4; o = lane, pc walks 0..35 per thread.
    // STS banks = o = lane -> conflict-free. Global reads per thread are
    // sequential 16B chunks along p for a fixed o (L1-friendly).
    {
        const float4* wg = (const float4*)(weights + (size_t)loc * (COUT * Pp));
        const int o = lane32;
        #pragma unroll
        for (int i = 0; i < 18; ++i) {
            int pc = (tid >> 5) + 2 * i;          // 0..35
            float4 v = wg[o * 36 + pc];
            int p = pc * 4;
            wsT[p][o]     = v.x;
            wsT[p + 1][o] = v.y;
            wsT[p + 2][o] = v.z;
            wsT[p + 3][o] = v.w;
        }
    }
    if (tid < COUT) bs[tid] = bias[loc * COUT + tid];

    // ---------------- stage x patches (transpose to xsT[p][b]) ----------------
    // b = lane -> STS banks distinct; (ci,kh) constant per warp per iter.
    {
        const int b = lane32;
        #pragma unroll
        for (int i = 0; i < 24; ++i) {
            int rest = (tid >> 5) + 2 * i;        // 0..47
            int kh = rest % 3;
            int ci = rest / 3;                    // 0..15
            int hh = h + kh - 1;
            float v0 = 0.f, v1 = 0.f, v2 = 0.f;
            if ((unsigned)hh < (unsigned)Hh) {
                const float* xrow = x + (((size_t)b * CIN + ci) * Hh + hh) * Ww;
                if (w > 0)      v0 = xrow[w - 1];
                v1 = xrow[w];
                if (w < Ww - 1) v2 = xrow[w + 1];
            }
            int p = ci * 9 + kh * 3;
            xsT[p][b]     = v0;
            xsT[p + 1][b] = v1;
            xsT[p + 2][b] = v2;
        }
    }
    __syncthreads();

    // ---------------- compute: 4b x 4o per thread, packed f32x2 ----------------
    const int tx = tid & 7;              // o-tile: o = tx*4 .. +3
    const int ty = tid >> 3;             // b-tile: b = ty*4 .. +3
    const int ob = tx * 4;
    const int bb = ty * 4;

    u64 acc[2][4];                        // [b-pair][o]
    #pragma unroll
    for (int i = 0; i < 2; ++i)
        #pragma unroll
        for (int j = 0; j < 4; ++j)
            acc[i][j] = 0ull;

    #pragma unroll 8
    for (int p = 0; p < Pp; ++p) {
        // x: {b0,b1},{b2,b3} pre-packed by the 16B load
        ulonglong2 xv = *(const ulonglong2*)(&xsT[p][bb]);
        float4 wv = *(const float4*)(&wsT[p][ob]);
        u64 w0 = pack2(wv.x);
        u64 w1 = pack2(wv.y);
        u64 w2 = pack2(wv.z);
        u64 w3 = pack2(wv.w);
        fma2(acc[0][0], xv.x, w0); fma2(acc[1][0], xv.y, w0);
        fma2(acc[0][1], xv.x, w1); fma2(acc[1][1], xv.y, w1);
        fma2(acc[0][2], xv.x, w2); fma2(acc[1][2], xv.y, w2);
        fma2(acc[0][3], xv.x, w3); fma2(acc[1][3], xv.y, w3);
    }

    // ---------------- epilogue: out[b][o][h][w] = acc + bias[o] ----------------
    #pragma unroll
    for (int i = 0; i < 2; ++i) {
        #pragma unroll
        for (int j = 0; j < 4; ++j) {
            float lo, hi;
            unpack2(acc[i][j], lo, hi);
            int o_ = ob + j;
            float bval = bs[o_];
            int b0 = bb + 2 * i;
            out[((size_t)b0 * COUT + o_) * (Hh * Ww) + loc]       = lo + bval;
            out[((size_t)(b0 + 1) * COUT + o_) * (Hh * Ww) + loc] = hi + bval;
        }
    }
}

extern "C" void kernel_launch(void* const* d_in, const int* in_sizes, int n_in,
                              void* d_out, int out_size) {
    const float* x       = (const float*)d_in[0];
    const float* weights = (const float*)d_in[1];
    const float* bias    = (const float*)d_in[2];
    float* out = (float*)d_out;
    (void)in_sizes; (void)n_in; (void)out_size;

    xonv_kernel<<<Hh * Ww, 64>>>(x, weights, bias, out);
}